// round 1
// baseline (speedup 1.0000x reference)
#include <cuda_runtime.h>
#include <math_constants.h>

#define BATCH   4
#define N_TOK   2048
#define DIM     1024
#define HEADS   16
#define DHEAD   64
#define INNER   1024
#define SCALE_F 0.125f
#define QPAD    68   // 68 floats = 272 B, 16B-aligned rows, bank-conflict-free transposed access

// Scratch (allocation inside kernel_launch is forbidden; __device__ globals are the sanctioned path)
__device__ float g_q  [BATCH * N_TOK * INNER];     // (x @ w_q)   [b*n, 1024]
__device__ float g_kv [BATCH * N_TOK * 2 * DHEAD]; // (x @ w_kv)  [b*n, 128]  (k = cols 0..63, v = 64..127)
__device__ float g_att[BATCH * N_TOK * INNER];     // attention output, [b*n, h*d]

// ---------------------------------------------------------------------------
// Tiled fp32 GEMM: C[M,N] = A[M,K] @ B[K,N] (+ bias[n]); all row-major.
// Block tile 64x64, K-tile 16, 256 threads, 4x4 register tile per thread.
// A staged transposed in smem so both fragments load as float4.
// ---------------------------------------------------------------------------
__global__ __launch_bounds__(256) void sgemm64(
    const float* __restrict__ A, const float* __restrict__ Bm,
    const float* __restrict__ bias, float* __restrict__ C,
    int M, int N, int K)
{
    __shared__ float As[16][64];   // As[k][m]
    __shared__ float Bs[16][64];   // Bs[k][n]

    const int tid = threadIdx.x;
    const int tx  = tid & 15;      // n-direction
    const int ty  = tid >> 4;      // m-direction
    const int m0  = blockIdx.y << 6;
    const int n0  = blockIdx.x << 6;

    float acc[4][4] = {};

    const int arow = tid >> 2;          // 0..63
    const int acol = (tid & 3) << 2;    // 0,4,8,12
    const int brow = tid >> 4;          // 0..15
    const int bcol = (tid & 15) << 2;   // 0..60

    const float* Ap = A  + (m0 + arow) * K + acol;
    const float* Bp = Bm + brow * N + n0 + bcol;

    for (int k0 = 0; k0 < K; k0 += 16) {
        float4 a4 = *(const float4*)(Ap + k0);
        float4 b4 = *(const float4*)(Bp + k0 * N);
        As[acol + 0][arow] = a4.x;
        As[acol + 1][arow] = a4.y;
        As[acol + 2][arow] = a4.z;
        As[acol + 3][arow] = a4.w;
        *(float4*)&Bs[brow][bcol] = b4;
        __syncthreads();

        #pragma unroll
        for (int k = 0; k < 16; ++k) {
            float4 av = *(const float4*)&As[k][ty << 2];
            float4 bv = *(const float4*)&Bs[k][tx << 2];
            float af[4] = {av.x, av.y, av.z, av.w};
            float bf[4] = {bv.x, bv.y, bv.z, bv.w};
            #pragma unroll
            for (int i = 0; i < 4; ++i)
                #pragma unroll
                for (int j = 0; j < 4; ++j)
                    acc[i][j] = fmaf(af[i], bf[j], acc[i][j]);
        }
        __syncthreads();
    }

    float4 bias4 = make_float4(0.f, 0.f, 0.f, 0.f);
    if (bias) bias4 = *(const float4*)&bias[n0 + (tx << 2)];

    #pragma unroll
    for (int i = 0; i < 4; ++i) {
        float4 o;
        o.x = acc[i][0] + bias4.x;
        o.y = acc[i][1] + bias4.y;
        o.z = acc[i][2] + bias4.z;
        o.w = acc[i][3] + bias4.w;
        *(float4*)&C[(m0 + (ty << 2) + i) * N + n0 + (tx << 2)] = o;
    }
}

// ---------------------------------------------------------------------------
// Flash attention, fp32. One CTA = (64 queries) x (one b,h). 256 threads as
// 16x16; each thread owns a 4x4 tile of S/P and of O (rows ty*4+i, cols tx*4+j).
// Online softmax via width-16 shfl reductions (a row's 16 owners share a
// half-warp). K stored transposed in smem (pad 68) for conflict-free f4 reads.
// ---------------------------------------------------------------------------
__global__ __launch_bounds__(256) void attn_kernel(
    const float* __restrict__ q, const float* __restrict__ kv,
    float* __restrict__ out)
{
    extern __shared__ float sm[];
    float* Qs  = sm;                  // [64][QPAD]  q rows x d
    float* Kts = Qs  + 64 * QPAD;     // [64][QPAD]  Kts[d][kj]  (transposed)
    float* Vs  = Kts + 64 * QPAD;     // [64][64]    kj x d
    float* Ps  = Vs  + 64 * 64;       // [64][64]    q rows x kj

    const int tid = threadIdx.x;
    const int tx  = tid & 15;
    const int ty  = tid >> 4;
    const int q0  = blockIdx.x << 6;
    const int h   = blockIdx.y;
    const int b   = blockIdx.z;

    // --- load Q tile (64x64) ---
    {
        const int row = tid >> 2, seg = tid & 3;
        const float* qp = q + (b * N_TOK + q0 + row) * INNER + h * DHEAD;
        #pragma unroll
        for (int i = 0; i < 4; ++i) {
            int d0 = seg * 16 + i * 4;
            *(float4*)(Qs + row * QPAD + d0) = *(const float4*)(qp + d0);
        }
    }

    float O[4][4] = {};
    float m_i[4], l_i[4];
    #pragma unroll
    for (int i = 0; i < 4; ++i) { m_i[i] = -CUDART_INF_F; l_i[i] = 0.f; }

    for (int k0 = 0; k0 < N_TOK; k0 += 64) {
        // --- load K (transposed) and V tiles ---
        {
            const int row = tid >> 2, seg = tid & 3;
            const float* kvp = kv + (b * N_TOK + k0 + row) * (2 * DHEAD);
            #pragma unroll
            for (int i = 0; i < 4; ++i) {
                int d0 = seg * 16 + i * 4;
                float4 k4 = *(const float4*)(kvp + d0);
                float4 v4 = *(const float4*)(kvp + DHEAD + d0);
                Kts[(d0 + 0) * QPAD + row] = k4.x;
                Kts[(d0 + 1) * QPAD + row] = k4.y;
                Kts[(d0 + 2) * QPAD + row] = k4.z;
                Kts[(d0 + 3) * QPAD + row] = k4.w;
                *(float4*)(Vs + row * 64 + d0) = v4;
            }
        }
        __syncthreads();   // also covers the one-time Q load on the first iter

        // --- S = Q @ K^T ---
        float S[4][4] = {};
        #pragma unroll 4
        for (int d = 0; d < 64; ++d) {
            float af[4];
            #pragma unroll
            for (int i = 0; i < 4; ++i) af[i] = Qs[(ty * 4 + i) * QPAD + d];
            float4 bv = *(const float4*)(Kts + d * QPAD + (tx << 2));
            float bf[4] = {bv.x, bv.y, bv.z, bv.w};
            #pragma unroll
            for (int i = 0; i < 4; ++i)
                #pragma unroll
                for (int j = 0; j < 4; ++j)
                    S[i][j] = fmaf(af[i], bf[j], S[i][j]);
        }

        // --- online softmax (per row; 16 owners of a row share a half-warp) ---
        #pragma unroll
        for (int i = 0; i < 4; ++i) {
            #pragma unroll
            for (int j = 0; j < 4; ++j) S[i][j] *= SCALE_F;

            float mt = fmaxf(fmaxf(S[i][0], S[i][1]), fmaxf(S[i][2], S[i][3]));
            mt = fmaxf(mt, __shfl_xor_sync(0xffffffffu, mt, 1));
            mt = fmaxf(mt, __shfl_xor_sync(0xffffffffu, mt, 2));
            mt = fmaxf(mt, __shfl_xor_sync(0xffffffffu, mt, 4));
            mt = fmaxf(mt, __shfl_xor_sync(0xffffffffu, mt, 8));

            float m_new = fmaxf(m_i[i], mt);
            float alpha = __expf(m_i[i] - m_new);

            float4 p;
            p.x = __expf(S[i][0] - m_new);
            p.y = __expf(S[i][1] - m_new);
            p.z = __expf(S[i][2] - m_new);
            p.w = __expf(S[i][3] - m_new);

            float rs = p.x + p.y + p.z + p.w;
            rs += __shfl_xor_sync(0xffffffffu, rs, 1);
            rs += __shfl_xor_sync(0xffffffffu, rs, 2);
            rs += __shfl_xor_sync(0xffffffffu, rs, 4);
            rs += __shfl_xor_sync(0xffffffffu, rs, 8);

            l_i[i] = l_i[i] * alpha + rs;
            m_i[i] = m_new;
            #pragma unroll
            for (int j = 0; j < 4; ++j) O[i][j] *= alpha;

            *(float4*)(Ps + (ty * 4 + i) * 64 + (tx << 2)) = p;
        }
        __syncthreads();

        // --- O += P @ V ---
        #pragma unroll 4
        for (int kk = 0; kk < 64; ++kk) {
            float af[4];
            #pragma unroll
            for (int i = 0; i < 4; ++i) af[i] = Ps[(ty * 4 + i) * 64 + kk];
            float4 bv = *(const float4*)(Vs + kk * 64 + (tx << 2));
            float bf[4] = {bv.x, bv.y, bv.z, bv.w};
            #pragma unroll
            for (int i = 0; i < 4; ++i)
                #pragma unroll
                for (int j = 0; j < 4; ++j)
                    O[i][j] = fmaf(af[i], bf[j], O[i][j]);
        }
        __syncthreads();
    }

    // --- epilogue: normalize and write [b, n, h*d] ---
    #pragma unroll
    for (int i = 0; i < 4; ++i) {
        float inv = 1.f / l_i[i];
        float4 o = make_float4(O[i][0] * inv, O[i][1] * inv,
                               O[i][2] * inv, O[i][3] * inv);
        *(float4*)(out + (b * N_TOK + q0 + ty * 4 + i) * INNER
                       + h * DHEAD + (tx << 2)) = o;
    }
}

// ---------------------------------------------------------------------------
extern "C" void kernel_launch(void* const* d_in, const int* in_sizes, int n_in,
                              void* d_out, int out_size)
{
    (void)in_sizes; (void)n_in; (void)out_size;
    const float* x     = (const float*)d_in[0];
    const float* w_q   = (const float*)d_in[1];
    const float* w_kv  = (const float*)d_in[2];
    const float* w_out = (const float*)d_in[3];
    const float* b_out = (const float*)d_in[4];
    float* out = (float*)d_out;

    float *pq, *pkv, *patt;
    cudaGetSymbolAddress((void**)&pq,   g_q);
    cudaGetSymbolAddress((void**)&pkv,  g_kv);
    cudaGetSymbolAddress((void**)&patt, g_att);

    const int M = BATCH * N_TOK;  // 8192

    // Q projection: [8192,1024] @ [1024,1024]
    sgemm64<<<dim3(INNER / 64, M / 64), 256>>>(x, w_q, nullptr, pq, M, INNER, DIM);
    // KV projection: [8192,1024] @ [1024,128]
    sgemm64<<<dim3((2 * DHEAD) / 64, M / 64), 256>>>(x, w_kv, nullptr, pkv, M, 2 * DHEAD, DIM);

    // Flash attention
    const size_t ATTN_SMEM = (size_t)(64 * QPAD * 2 + 64 * 64 * 2) * sizeof(float); // 67584 B
    cudaFuncSetAttribute(attn_kernel, cudaFuncAttributeMaxDynamicSharedMemorySize,
                         (int)ATTN_SMEM);
    attn_kernel<<<dim3(N_TOK / 64, HEADS, BATCH), 256, ATTN_SMEM>>>(pq, pkv, patt);

    // Output projection + bias: [8192,1024] @ [1024,1024] + b
    sgemm64<<<dim3(DIM / 64, M / 64), 256>>>(patt, w_out, b_out, out, M, DIM, DIM);
}

// round 3
// speedup vs baseline: 2.9517x; 2.9517x over previous
#include <cuda_runtime.h>
#include <cuda_bf16.h>
#include <math_constants.h>
#include <cstdint>

#define BATCH   4
#define N_TOK   2048
#define DIM     1024
#define HEADS   16
#define DHEAD   64
#define INNER   1024
#define SCALE_F 0.125f
#define MROWS   8192        // BATCH * N_TOK

// ---------------- scratch (device globals; allocation is forbidden) --------
__device__ __nv_bfloat16 g_xh [MROWS * DIM];        // x split hi
__device__ __nv_bfloat16 g_xl [MROWS * DIM];        // x split lo
__device__ __nv_bfloat16 g_wqh[INNER * DIM];        // w_q^T split  [N][K]
__device__ __nv_bfloat16 g_wql[INNER * DIM];
__device__ __nv_bfloat16 g_wkh[2 * DHEAD * DIM];    // w_kv^T split [128][1024]
__device__ __nv_bfloat16 g_wkl[2 * DHEAD * DIM];
__device__ __nv_bfloat16 g_woh[DIM * INNER];        // w_out^T split
__device__ __nv_bfloat16 g_wol[DIM * INNER];
__device__ __nv_bfloat16 g_qh [MROWS * INNER];      // q = x@w_q, split
__device__ __nv_bfloat16 g_ql [MROWS * INNER];
__device__ __nv_bfloat16 g_kh [MROWS * DHEAD];      // k split  [tok][d]
__device__ __nv_bfloat16 g_kl [MROWS * DHEAD];
__device__ __nv_bfloat16 g_vth[BATCH * DHEAD * N_TOK]; // v^T split [b][d][tok]
__device__ __nv_bfloat16 g_vtl[BATCH * DHEAD * N_TOK];
__device__ __nv_bfloat16 g_ah [MROWS * INNER];      // attention out, split
__device__ __nv_bfloat16 g_al [MROWS * INNER];

// ---------------- helpers --------------------------------------------------
__device__ __forceinline__ uint32_t smem_u32(const void* p) {
    return (uint32_t)__cvta_generic_to_shared(p);
}

__device__ __forceinline__ void ldsm4(uint32_t& r0, uint32_t& r1,
                                      uint32_t& r2, uint32_t& r3, uint32_t a) {
    asm volatile("ldmatrix.sync.aligned.m8n8.x4.shared.b16 {%0,%1,%2,%3}, [%4];\n"
                 : "=r"(r0), "=r"(r1), "=r"(r2), "=r"(r3) : "r"(a));
}

__device__ __forceinline__ void mma16816(float* c,
        uint32_t a0, uint32_t a1, uint32_t a2, uint32_t a3,
        uint32_t b0, uint32_t b1) {
    asm volatile(
        "mma.sync.aligned.m16n8k16.row.col.f32.bf16.bf16.f32 "
        "{%0,%1,%2,%3}, {%4,%5,%6,%7}, {%8,%9}, {%0,%1,%2,%3};\n"
        : "+f"(c[0]), "+f"(c[1]), "+f"(c[2]), "+f"(c[3])
        : "r"(a0), "r"(a1), "r"(a2), "r"(a3), "r"(b0), "r"(b1));
}

// split fp32 value into hi/lo bf16 (v = hi + lo + O(2^-18 v))
__device__ __forceinline__ void split1(float v, __nv_bfloat16& h, __nv_bfloat16& l) {
    h = __float2bfloat16(v);
    l = __float2bfloat16(v - __bfloat162float(h));
}
// pack two fp32 into packed-bf16x2 hi word + lo word
__device__ __forceinline__ void split_pack(float x, float y, uint32_t& hi, uint32_t& lo) {
    __nv_bfloat16 hx, lx, hy, ly;
    split1(x, hx, lx);
    split1(y, hy, ly);
    hi = ((uint32_t)__bfloat16_as_ushort(hy) << 16) | __bfloat16_as_ushort(hx);
    lo = ((uint32_t)__bfloat16_as_ushort(ly) << 16) | __bfloat16_as_ushort(lx);
}

// ---------------- split kernels --------------------------------------------
__global__ void split_f32(const float4* __restrict__ in,
                          uint2* __restrict__ oh, uint2* __restrict__ ol, int n4) {
    int i = blockIdx.x * blockDim.x + threadIdx.x;
    if (i >= n4) return;
    float4 v = in[i];
    uint32_t h0, l0, h1, l1;
    split_pack(v.x, v.y, h0, l0);
    split_pack(v.z, v.w, h1, l1);
    oh[i] = make_uint2(h0, h1);
    ol[i] = make_uint2(l0, l1);
}

// in [R][C] fp32 -> out hi/lo [C][R] bf16
__global__ void transpose_split(const float* __restrict__ in,
                                __nv_bfloat16* __restrict__ oh,
                                __nv_bfloat16* __restrict__ ol, int R, int C) {
    __shared__ float t[32][33];
    int c0 = blockIdx.x * 32, r0 = blockIdx.y * 32;
    int x = threadIdx.x, y = threadIdx.y;
    #pragma unroll
    for (int i = 0; i < 32; i += 8)
        t[y + i][x] = in[(size_t)(r0 + y + i) * C + c0 + x];
    __syncthreads();
    #pragma unroll
    for (int i = 0; i < 32; i += 8) {
        float v = t[x][y + i];
        __nv_bfloat16 h, l;
        split1(v, h, l);
        size_t idx = (size_t)(c0 + y + i) * R + r0 + x;
        oh[idx] = h;
        ol[idx] = l;
    }
}

// ---------------- GEMM: C[M,N] = A[M,K] @ B[K,N] ---------------------------
// A as split bf16 row-major [M][K]; B as split bf16 TRANSPOSED [N][K].
// CTA tile 128x128, K-step 32, 8 warps (4x2), warp tile 32x64, mma m16n8k16,
// 3-mma error-compensated accumulation in fp32.
// mode 0: Cf = C + bias (fp32).  mode 1: split C -> Chi/Clo.
// mode 2: kv special: cols<64 -> K split [tok][64]; cols>=64 -> V^T split [b][d][tok].
#define KSTEP 32
#define SPAD  40   // 32 + 8, 80B rows (odd multiple of 16B -> LDSM conflict-free)

__global__ __launch_bounds__(256, 2) void gemm_bf16s(
    const __nv_bfloat16* __restrict__ Ah, const __nv_bfloat16* __restrict__ Al,
    const __nv_bfloat16* __restrict__ Bh, const __nv_bfloat16* __restrict__ Bl,
    const float* __restrict__ bias,
    float* __restrict__ Cf,
    __nv_bfloat16* __restrict__ Chi, __nv_bfloat16* __restrict__ Clo,
    __nv_bfloat16* __restrict__ Khi, __nv_bfloat16* __restrict__ Klo,
    __nv_bfloat16* __restrict__ Vth, __nv_bfloat16* __restrict__ Vtl,
    int M, int N, int K, int mode)
{
    __shared__ __nv_bfloat16 As_h[128 * SPAD];
    __shared__ __nv_bfloat16 As_l[128 * SPAD];
    __shared__ __nv_bfloat16 Bs_h[128 * SPAD];
    __shared__ __nv_bfloat16 Bs_l[128 * SPAD];

    const int tid  = threadIdx.x;
    const int lane = tid & 31;
    const int wid  = tid >> 5;
    const int wm   = wid & 3;       // 4 m-warps
    const int wn   = wid >> 2;      // 2 n-warps
    const int m0   = blockIdx.y << 7;
    const int n0   = blockIdx.x << 7;

    float c[2][8][4];
    #pragma unroll
    for (int i = 0; i < 2; ++i)
        #pragma unroll
        for (int j = 0; j < 8; ++j)
            #pragma unroll
            for (int q = 0; q < 4; ++q) c[i][j][q] = 0.f;

    const int lrow = tid >> 1;            // 0..127
    const int lch  = (tid & 1) * 2;       // chunk base (8 bf16 chunks)

    for (int k0 = 0; k0 < K; k0 += KSTEP) {
        // load A/B tiles (each thread: 2 x 16B per array)
        #pragma unroll
        for (int cc = 0; cc < 2; ++cc) {
            int ch = lch + cc;
            size_t ga = (size_t)(m0 + lrow) * K + k0 + ch * 8;
            size_t gb = (size_t)(n0 + lrow) * K + k0 + ch * 8;
            int sidx = lrow * SPAD + ch * 8;
            *(uint4*)&As_h[sidx] = *(const uint4*)&Ah[ga];
            *(uint4*)&As_l[sidx] = *(const uint4*)&Al[ga];
            *(uint4*)&Bs_h[sidx] = *(const uint4*)&Bh[gb];
            *(uint4*)&Bs_l[sidx] = *(const uint4*)&Bl[gb];
        }
        __syncthreads();

        #pragma unroll
        for (int ks = 0; ks < KSTEP; ks += 16) {
            // A fragments (hi & lo), 2 m-tiles
            uint32_t afh[2][4], afl[2][4];
            #pragma unroll
            for (int mt = 0; mt < 2; ++mt) {
                int ar = wm * 32 + mt * 16 + (lane & 15);
                int ac = ks + ((lane >> 4) << 3);
                ldsm4(afh[mt][0], afh[mt][1], afh[mt][2], afh[mt][3],
                      smem_u32(&As_h[ar * SPAD + ac]));
                ldsm4(afl[mt][0], afl[mt][1], afl[mt][2], afl[mt][3],
                      smem_u32(&As_l[ar * SPAD + ac]));
            }
            // B fragments per n-pair
            #pragma unroll
            for (int p = 0; p < 4; ++p) {
                int br = wn * 64 + p * 16 + (lane & 7) + ((lane >> 4) << 3);
                int bc = ks + (((lane >> 3) & 1) << 3);
                uint32_t bh0, bh1, bh2, bh3, bl0, bl1, bl2, bl3;
                ldsm4(bh0, bh1, bh2, bh3, smem_u32(&Bs_h[br * SPAD + bc]));
                ldsm4(bl0, bl1, bl2, bl3, smem_u32(&Bs_l[br * SPAD + bc]));
                #pragma unroll
                for (int mt = 0; mt < 2; ++mt) {
                    mma16816(c[mt][2 * p], afh[mt][0], afh[mt][1], afh[mt][2], afh[mt][3], bh0, bh1);
                    mma16816(c[mt][2 * p], afh[mt][0], afh[mt][1], afh[mt][2], afh[mt][3], bl0, bl1);
                    mma16816(c[mt][2 * p], afl[mt][0], afl[mt][1], afl[mt][2], afl[mt][3], bh0, bh1);
                    mma16816(c[mt][2 * p + 1], afh[mt][0], afh[mt][1], afh[mt][2], afh[mt][3], bh2, bh3);
                    mma16816(c[mt][2 * p + 1], afh[mt][0], afh[mt][1], afh[mt][2], afh[mt][3], bl2, bl3);
                    mma16816(c[mt][2 * p + 1], afl[mt][0], afl[mt][1], afl[mt][2], afl[mt][3], bh2, bh3);
                }
            }
        }
        __syncthreads();
    }

    // epilogue
    const int r  = lane >> 2;
    const int cq = (lane & 3) * 2;
    #pragma unroll
    for (int mt = 0; mt < 2; ++mt) {
        #pragma unroll
        for (int nt = 0; nt < 8; ++nt) {
            int row = m0 + wm * 32 + mt * 16 + r;
            int col = n0 + wn * 64 + nt * 8 + cq;
            float* cc = c[mt][nt];
            if (mode == 0) {
                float b0 = bias[col], b1 = bias[col + 1];
                *(float2*)&Cf[(size_t)row * N + col] = make_float2(cc[0] + b0, cc[1] + b1);
                *(float2*)&Cf[(size_t)(row + 8) * N + col] = make_float2(cc[2] + b0, cc[3] + b1);
            } else if (mode == 1) {
                uint32_t h, l;
                split_pack(cc[0], cc[1], h, l);
                *(uint32_t*)&Chi[(size_t)row * N + col] = h;
                *(uint32_t*)&Clo[(size_t)row * N + col] = l;
                split_pack(cc[2], cc[3], h, l);
                *(uint32_t*)&Chi[(size_t)(row + 8) * N + col] = h;
                *(uint32_t*)&Clo[(size_t)(row + 8) * N + col] = l;
            } else {
                if (col < DHEAD) {
                    uint32_t h, l;
                    split_pack(cc[0], cc[1], h, l);
                    *(uint32_t*)&Khi[(size_t)row * DHEAD + col] = h;
                    *(uint32_t*)&Klo[(size_t)row * DHEAD + col] = l;
                    split_pack(cc[2], cc[3], h, l);
                    *(uint32_t*)&Khi[(size_t)(row + 8) * DHEAD + col] = h;
                    *(uint32_t*)&Klo[(size_t)(row + 8) * DHEAD + col] = l;
                } else {
                    int d = col - DHEAD;
                    int b = row >> 11, tok = row & 2047;
                    #pragma unroll
                    for (int e = 0; e < 2; ++e) {
                        __nv_bfloat16 h, l;
                        size_t base = ((size_t)(b * DHEAD + d + e)) * N_TOK;
                        split1(cc[e], h, l);
                        Vth[base + tok] = h; Vtl[base + tok] = l;
                        split1(cc[2 + e], h, l);
                        Vth[base + tok + 8] = h; Vtl[base + tok + 8] = l;
                    }
                }
            }
        }
    }
}

// ---------------- flash attention on tensor cores --------------------------
// CTA: 128 q-rows x one (b,h). 8 warps, each warp owns 16 q-rows.
// kv chunks of 64. S & P stay in register fragments; P split to bf16 hi/lo
// in-register (S-frag layout == A-frag layout for the PV mma).
#define QPAD2 72   // 144B rows (odd multiple of 16B) -> conflict-free LDSM

__global__ __launch_bounds__(256, 2) void attn_mma(
    const __nv_bfloat16* __restrict__ qh, const __nv_bfloat16* __restrict__ ql,
    const __nv_bfloat16* __restrict__ kh, const __nv_bfloat16* __restrict__ kl,
    const __nv_bfloat16* __restrict__ vth, const __nv_bfloat16* __restrict__ vtl,
    __nv_bfloat16* __restrict__ oh, __nv_bfloat16* __restrict__ ol)
{
    extern __shared__ __nv_bfloat16 sm[];
    __nv_bfloat16* Qh = sm;                       // [128][QPAD2]
    __nv_bfloat16* Ql = Qh + 128 * QPAD2;
    __nv_bfloat16* Kh = Ql + 128 * QPAD2;         // [64][QPAD2]
    __nv_bfloat16* Kl = Kh + 64 * QPAD2;
    __nv_bfloat16* Vh = Kl + 64 * QPAD2;          // [64 d][QPAD2 tok]
    __nv_bfloat16* Vl = Vh + 64 * QPAD2;

    const int tid  = threadIdx.x;
    const int lane = tid & 31;
    const int wid  = tid >> 5;
    const int q0   = blockIdx.x << 7;
    const int h    = blockIdx.y;
    const int b    = blockIdx.z;
    const int wrow = wid * 16;

    // load Q tile (128 x 64) hi+lo
    {
        #pragma unroll
        for (int it = 0; it < 4; ++it) {
            int e = tid + it * 256;              // 0..1023
            int row = e >> 3, ch = e & 7;
            size_t g = (size_t)(b * N_TOK + q0 + row) * INNER + h * DHEAD + ch * 8;
            int s = row * QPAD2 + ch * 8;
            *(uint4*)&Qh[s] = *(const uint4*)&qh[g];
            *(uint4*)&Ql[s] = *(const uint4*)&ql[g];
        }
    }

    float oc[8][4];
    #pragma unroll
    for (int j = 0; j < 8; ++j)
        #pragma unroll
        for (int q = 0; q < 4; ++q) oc[j][q] = 0.f;
    float mst[2] = {-CUDART_INF_F, -CUDART_INF_F};
    float lst[2] = {0.f, 0.f};

    for (int kv0 = 0; kv0 < N_TOK; kv0 += 64) {
        __syncthreads();   // prev chunk's mma done before overwrite (also covers Q load)
        #pragma unroll
        for (int it = 0; it < 2; ++it) {
            int e = tid + it * 256;              // 0..511
            int row = e >> 3, ch = e & 7;
            size_t gk = (size_t)(b * N_TOK + kv0 + row) * DHEAD + ch * 8;
            size_t gv = (size_t)(b * DHEAD + row) * N_TOK + kv0 + ch * 8;
            int s = row * QPAD2 + ch * 8;
            *(uint4*)&Kh[s] = *(const uint4*)&kh[gk];
            *(uint4*)&Kl[s] = *(const uint4*)&kl[gk];
            *(uint4*)&Vh[s] = *(const uint4*)&vth[gv];
            *(uint4*)&Vl[s] = *(const uint4*)&vtl[gv];
        }
        __syncthreads();

        // ---- S = Q @ K^T (16 x 64 per warp) ----
        float sc[8][4];
        #pragma unroll
        for (int j = 0; j < 8; ++j)
            #pragma unroll
            for (int q = 0; q < 4; ++q) sc[j][q] = 0.f;

        #pragma unroll
        for (int ks = 0; ks < 4; ++ks) {
            uint32_t ah0[4], al0[4];
            int ar = wrow + (lane & 15);
            int ac = ks * 16 + ((lane >> 4) << 3);
            ldsm4(ah0[0], ah0[1], ah0[2], ah0[3], smem_u32(&Qh[ar * QPAD2 + ac]));
            ldsm4(al0[0], al0[1], al0[2], al0[3], smem_u32(&Ql[ar * QPAD2 + ac]));
            #pragma unroll
            for (int p = 0; p < 4; ++p) {
                int br = p * 16 + (lane & 7) + ((lane >> 4) << 3);
                int bc = ks * 16 + (((lane >> 3) & 1) << 3);
                uint32_t bh0, bh1, bh2, bh3, bl0, bl1, bl2, bl3;
                ldsm4(bh0, bh1, bh2, bh3, smem_u32(&Kh[br * QPAD2 + bc]));
                ldsm4(bl0, bl1, bl2, bl3, smem_u32(&Kl[br * QPAD2 + bc]));
                mma16816(sc[2 * p],     ah0[0], ah0[1], ah0[2], ah0[3], bh0, bh1);
                mma16816(sc[2 * p],     ah0[0], ah0[1], ah0[2], ah0[3], bl0, bl1);
                mma16816(sc[2 * p],     al0[0], al0[1], al0[2], al0[3], bh0, bh1);
                mma16816(sc[2 * p + 1], ah0[0], ah0[1], ah0[2], ah0[3], bh2, bh3);
                mma16816(sc[2 * p + 1], ah0[0], ah0[1], ah0[2], ah0[3], bl2, bl3);
                mma16816(sc[2 * p + 1], al0[0], al0[1], al0[2], al0[3], bh2, bh3);
            }
        }

        // ---- online softmax on fragments ----
        #pragma unroll
        for (int hf = 0; hf < 2; ++hf) {
            float mx = -CUDART_INF_F;
            #pragma unroll
            for (int nt = 0; nt < 8; ++nt) {
                sc[nt][2 * hf]     *= SCALE_F;
                sc[nt][2 * hf + 1] *= SCALE_F;
                mx = fmaxf(mx, fmaxf(sc[nt][2 * hf], sc[nt][2 * hf + 1]));
            }
            mx = fmaxf(mx, __shfl_xor_sync(0xffffffffu, mx, 1));
            mx = fmaxf(mx, __shfl_xor_sync(0xffffffffu, mx, 2));
            float mn = fmaxf(mst[hf], mx);
            float alpha = __expf(mst[hf] - mn);
            float sum = 0.f;
            #pragma unroll
            for (int nt = 0; nt < 8; ++nt) {
                float p0 = __expf(sc[nt][2 * hf] - mn);
                float p1 = __expf(sc[nt][2 * hf + 1] - mn);
                sc[nt][2 * hf] = p0; sc[nt][2 * hf + 1] = p1;
                sum += p0 + p1;
            }
            sum += __shfl_xor_sync(0xffffffffu, sum, 1);
            sum += __shfl_xor_sync(0xffffffffu, sum, 2);
            lst[hf] = lst[hf] * alpha + sum;
            mst[hf] = mn;
            #pragma unroll
            for (int nt = 0; nt < 8; ++nt) {
                oc[nt][2 * hf]     *= alpha;
                oc[nt][2 * hf + 1] *= alpha;
            }
        }

        // ---- O += P @ V (P from fragments, split in-register) ----
        #pragma unroll
        for (int kt = 0; kt < 4; ++kt) {
            uint32_t pah[4], pal[4];
            split_pack(sc[2 * kt][0],     sc[2 * kt][1],     pah[0], pal[0]);
            split_pack(sc[2 * kt][2],     sc[2 * kt][3],     pah[1], pal[1]);
            split_pack(sc[2 * kt + 1][0], sc[2 * kt + 1][1], pah[2], pal[2]);
            split_pack(sc[2 * kt + 1][2], sc[2 * kt + 1][3], pah[3], pal[3]);
            #pragma unroll
            for (int p = 0; p < 4; ++p) {
                int br = p * 16 + (lane & 7) + ((lane >> 4) << 3);
                int bc = kt * 16 + (((lane >> 3) & 1) << 3);
                uint32_t vh0, vh1, vh2, vh3, vl0, vl1, vl2, vl3;
                ldsm4(vh0, vh1, vh2, vh3, smem_u32(&Vh[br * QPAD2 + bc]));
                ldsm4(vl0, vl1, vl2, vl3, smem_u32(&Vl[br * QPAD2 + bc]));
                mma16816(oc[2 * p],     pah[0], pah[1], pah[2], pah[3], vh0, vh1);
                mma16816(oc[2 * p],     pah[0], pah[1], pah[2], pah[3], vl0, vl1);
                mma16816(oc[2 * p],     pal[0], pal[1], pal[2], pal[3], vh0, vh1);
                mma16816(oc[2 * p + 1], pah[0], pah[1], pah[2], pah[3], vh2, vh3);
                mma16816(oc[2 * p + 1], pah[0], pah[1], pah[2], pah[3], vl2, vl3);
                mma16816(oc[2 * p + 1], pal[0], pal[1], pal[2], pal[3], vh2, vh3);
            }
        }
    }

    // ---- epilogue: normalize, split, write ----
    float inv0 = 1.f / lst[0], inv1 = 1.f / lst[1];
    const int r  = lane >> 2;
    const int cq = (lane & 3) * 2;
    #pragma unroll
    for (int nt = 0; nt < 8; ++nt) {
        int row = b * N_TOK + q0 + wrow + r;
        int col = h * DHEAD + nt * 8 + cq;
        uint32_t hw, lw;
        split_pack(oc[nt][0] * inv0, oc[nt][1] * inv0, hw, lw);
        *(uint32_t*)&oh[(size_t)row * INNER + col] = hw;
        *(uint32_t*)&ol[(size_t)row * INNER + col] = lw;
        split_pack(oc[nt][2] * inv1, oc[nt][3] * inv1, hw, lw);
        *(uint32_t*)&oh[(size_t)(row + 8) * INNER + col] = hw;
        *(uint32_t*)&ol[(size_t)(row + 8) * INNER + col] = lw;
    }
}

// ---------------------------------------------------------------------------
extern "C" void kernel_launch(void* const* d_in, const int* in_sizes, int n_in,
                              void* d_out, int out_size)
{
    (void)in_sizes; (void)n_in; (void)out_size;
    const float* x     = (const float*)d_in[0];
    const float* w_q   = (const float*)d_in[1];
    const float* w_kv  = (const float*)d_in[2];
    const float* w_out = (const float*)d_in[3];
    const float* b_out = (const float*)d_in[4];
    float* out = (float*)d_out;

    __nv_bfloat16 *xh, *xl, *wqh, *wql, *wkh, *wkl, *woh, *wol;
    __nv_bfloat16 *qhp, *qlp, *khp, *klp, *vth, *vtl, *ahp, *alp;
    cudaGetSymbolAddress((void**)&xh,  g_xh);  cudaGetSymbolAddress((void**)&xl,  g_xl);
    cudaGetSymbolAddress((void**)&wqh, g_wqh); cudaGetSymbolAddress((void**)&wql, g_wql);
    cudaGetSymbolAddress((void**)&wkh, g_wkh); cudaGetSymbolAddress((void**)&wkl, g_wkl);
    cudaGetSymbolAddress((void**)&woh, g_woh); cudaGetSymbolAddress((void**)&wol, g_wol);
    cudaGetSymbolAddress((void**)&qhp, g_qh);  cudaGetSymbolAddress((void**)&qlp, g_ql);
    cudaGetSymbolAddress((void**)&khp, g_kh);  cudaGetSymbolAddress((void**)&klp, g_kl);
    cudaGetSymbolAddress((void**)&vth, g_vth); cudaGetSymbolAddress((void**)&vtl, g_vtl);
    cudaGetSymbolAddress((void**)&ahp, g_ah);  cudaGetSymbolAddress((void**)&alp, g_al);

    // 1. split x
    split_f32<<<(MROWS * DIM / 4 + 255) / 256, 256>>>(
        (const float4*)x, (uint2*)xh, (uint2*)xl, MROWS * DIM / 4);
    // 2. transpose+split weights
    transpose_split<<<dim3(INNER / 32, DIM / 32), dim3(32, 8)>>>(w_q,  wqh, wql, DIM, INNER);
    transpose_split<<<dim3((2 * DHEAD) / 32, DIM / 32), dim3(32, 8)>>>(w_kv, wkh, wkl, DIM, 2 * DHEAD);
    transpose_split<<<dim3(DIM / 32, INNER / 32), dim3(32, 8)>>>(w_out, woh, wol, INNER, DIM);

    // 3. Q projection (mode 1: split output)
    gemm_bf16s<<<dim3(INNER / 128, MROWS / 128), 256>>>(
        xh, xl, wqh, wql, nullptr, nullptr, qhp, qlp,
        nullptr, nullptr, nullptr, nullptr, MROWS, INNER, DIM, 1);
    // 4. KV projection (mode 2: k split + v^T split)
    gemm_bf16s<<<dim3(1, MROWS / 128), 256>>>(
        xh, xl, wkh, wkl, nullptr, nullptr, nullptr, nullptr,
        khp, klp, vth, vtl, MROWS, 2 * DHEAD, DIM, 2);

    // 5. attention
    const size_t ASMEM = (size_t)(128 * QPAD2 * 2 + 64 * QPAD2 * 4) * sizeof(__nv_bfloat16);
    cudaFuncSetAttribute(attn_mma, cudaFuncAttributeMaxDynamicSharedMemorySize, (int)ASMEM);
    attn_mma<<<dim3(N_TOK / 128, HEADS, BATCH), 256, ASMEM>>>(
        qhp, qlp, khp, klp, vth, vtl, ahp, alp);

    // 6. output projection + bias (mode 0: fp32)
    gemm_bf16s<<<dim3(DIM / 128, MROWS / 128), 256>>>(
        ahp, alp, woh, wol, b_out, out, nullptr, nullptr,
        nullptr, nullptr, nullptr, nullptr, MROWS, DIM, INNER, 0);
}

// round 5
// speedup vs baseline: 3.2070x; 1.0865x over previous
#include <cuda_runtime.h>
#include <cuda_bf16.h>
#include <math_constants.h>
#include <cstdint>

#define BATCH   4
#define N_TOK   2048
#define DIM     1024
#define HEADS   16
#define DHEAD   64
#define INNER   1024
#define SCALE_F 0.125f
#define MROWS   8192        // BATCH * N_TOK

// ---------------- scratch (device globals; allocation is forbidden) --------
__device__ __nv_bfloat16 g_xh [MROWS * DIM];
__device__ __nv_bfloat16 g_xl [MROWS * DIM];
__device__ __nv_bfloat16 g_wqh[INNER * DIM];
__device__ __nv_bfloat16 g_wql[INNER * DIM];
__device__ __nv_bfloat16 g_wkh[2 * DHEAD * DIM];
__device__ __nv_bfloat16 g_wkl[2 * DHEAD * DIM];
__device__ __nv_bfloat16 g_woh[DIM * INNER];
__device__ __nv_bfloat16 g_wol[DIM * INNER];
__device__ __nv_bfloat16 g_qh [MROWS * INNER];
__device__ __nv_bfloat16 g_ql [MROWS * INNER];
__device__ __nv_bfloat16 g_kh [MROWS * DHEAD];
__device__ __nv_bfloat16 g_kl [MROWS * DHEAD];
__device__ __nv_bfloat16 g_vth[BATCH * DHEAD * N_TOK];
__device__ __nv_bfloat16 g_vtl[BATCH * DHEAD * N_TOK];
__device__ __nv_bfloat16 g_ah [MROWS * INNER];
__device__ __nv_bfloat16 g_al [MROWS * INNER];

// ---------------- helpers --------------------------------------------------
__device__ __forceinline__ uint32_t smem_u32(const void* p) {
    return (uint32_t)__cvta_generic_to_shared(p);
}

__device__ __forceinline__ void ldsm4(uint32_t& r0, uint32_t& r1,
                                      uint32_t& r2, uint32_t& r3, uint32_t a) {
    asm volatile("ldmatrix.sync.aligned.m8n8.x4.shared.b16 {%0,%1,%2,%3}, [%4];\n"
                 : "=r"(r0), "=r"(r1), "=r"(r2), "=r"(r3) : "r"(a));
}

__device__ __forceinline__ void mma16816(float* c,
        uint32_t a0, uint32_t a1, uint32_t a2, uint32_t a3,
        uint32_t b0, uint32_t b1) {
    asm volatile(
        "mma.sync.aligned.m16n8k16.row.col.f32.bf16.bf16.f32 "
        "{%0,%1,%2,%3}, {%4,%5,%6,%7}, {%8,%9}, {%0,%1,%2,%3};\n"
        : "+f"(c[0]), "+f"(c[1]), "+f"(c[2]), "+f"(c[3])
        : "r"(a0), "r"(a1), "r"(a2), "r"(a3), "r"(b0), "r"(b1));
}

__device__ __forceinline__ void split1(float v, __nv_bfloat16& h, __nv_bfloat16& l) {
    h = __float2bfloat16(v);
    l = __float2bfloat16(v - __bfloat162float(h));
}
__device__ __forceinline__ void split_pack(float x, float y, uint32_t& hi, uint32_t& lo) {
    __nv_bfloat16 hx, lx, hy, ly;
    split1(x, hx, lx);
    split1(y, hy, ly);
    hi = ((uint32_t)__bfloat16_as_ushort(hy) << 16) | __bfloat16_as_ushort(hx);
    lo = ((uint32_t)__bfloat16_as_ushort(ly) << 16) | __bfloat16_as_ushort(lx);
}

// cp.async (LDGSTS) primitives
#define CP16(dst, src) \
    asm volatile("cp.async.cg.shared.global [%0], [%1], 16;" :: "r"(dst), "l"(src))
#define CP_COMMIT() asm volatile("cp.async.commit_group;" ::: "memory")
#define CP_WAIT(n)  asm volatile("cp.async.wait_group %0;" :: "n"(n) : "memory")

// ---------------- split kernels --------------------------------------------
__global__ void split_f32(const float4* __restrict__ in,
                          uint2* __restrict__ oh, uint2* __restrict__ ol, int n4) {
    int i = blockIdx.x * blockDim.x + threadIdx.x;
    if (i >= n4) return;
    float4 v = in[i];
    uint32_t h0, l0, h1, l1;
    split_pack(v.x, v.y, h0, l0);
    split_pack(v.z, v.w, h1, l1);
    oh[i] = make_uint2(h0, h1);
    ol[i] = make_uint2(l0, l1);
}

__global__ void transpose_split(const float* __restrict__ in,
                                __nv_bfloat16* __restrict__ oh,
                                __nv_bfloat16* __restrict__ ol, int R, int C) {
    __shared__ float t[32][33];
    int c0 = blockIdx.x * 32, r0 = blockIdx.y * 32;
    int x = threadIdx.x, y = threadIdx.y;
    #pragma unroll
    for (int i = 0; i < 32; i += 8)
        t[y + i][x] = in[(size_t)(r0 + y + i) * C + c0 + x];
    __syncthreads();
    #pragma unroll
    for (int i = 0; i < 32; i += 8) {
        float v = t[x][y + i];
        __nv_bfloat16 h, l;
        split1(v, h, l);
        size_t idx = (size_t)(c0 + y + i) * R + r0 + x;
        oh[idx] = h;
        ol[idx] = l;
    }
}

// ---------------- GEMM with cp.async 2-stage pipeline ----------------------
// C[M,N] = A[M,K] @ B^T; A split bf16 [M][K], B split bf16 [N][K].
// CTA tile 128x128, K-step 32, 8 warps (4x2), warp tile 32x64, m16n8k16,
// 3-mma compensated accumulation in fp32.
#define KSTEP 32
#define SPAD  40                     // elements; 80-byte rows (LDSM conflict-free)
#define GST   (128 * SPAD * 2)       // 10240 B per array per stage
#define GSTAGE (4 * GST)             // 40960 B per stage
#define GSMEM  (2 * GSTAGE)          // 81920 B

__global__ __launch_bounds__(256, 2) void gemm_cp(
    const __nv_bfloat16* __restrict__ Ah, const __nv_bfloat16* __restrict__ Al,
    const __nv_bfloat16* __restrict__ Bh, const __nv_bfloat16* __restrict__ Bl,
    const float* __restrict__ bias,
    float* __restrict__ Cf,
    __nv_bfloat16* __restrict__ Chi, __nv_bfloat16* __restrict__ Clo,
    __nv_bfloat16* __restrict__ Khi, __nv_bfloat16* __restrict__ Klo,
    __nv_bfloat16* __restrict__ Vth, __nv_bfloat16* __restrict__ Vtl,
    int M, int N, int K, int mode)
{
    extern __shared__ char smem[];
    const uint32_t sb = smem_u32(smem);

    const int tid  = threadIdx.x;
    const int lane = tid & 31;
    const int wid  = tid >> 5;
    const int wm   = wid & 3;
    const int wn   = wid >> 2;
    const int m0   = blockIdx.y << 7;
    const int n0   = blockIdx.x << 7;

    float c[2][8][4];
    #pragma unroll
    for (int i = 0; i < 2; ++i)
        #pragma unroll
        for (int j = 0; j < 8; ++j)
            #pragma unroll
            for (int q = 0; q < 4; ++q) c[i][j][q] = 0.f;

    const int lrow = tid >> 1;
    const int lch  = (tid & 1) * 2;

    auto prefetch = [&](int ch, int s) {
        const uint32_t base = sb + s * GSTAGE;
        const int k0 = ch * KSTEP;
        #pragma unroll
        for (int cc = 0; cc < 2; ++cc) {
            int chn = lch + cc;
            size_t ga = (size_t)(m0 + lrow) * K + k0 + chn * 8;
            size_t gb = (size_t)(n0 + lrow) * K + k0 + chn * 8;
            uint32_t so = lrow * (SPAD * 2) + chn * 16;
            CP16(base + so,           &Ah[ga]);
            CP16(base + GST + so,     &Al[ga]);
            CP16(base + 2 * GST + so, &Bh[gb]);
            CP16(base + 3 * GST + so, &Bl[gb]);
        }
        CP_COMMIT();
    };

    const int nch = K / KSTEP;
    prefetch(0, 0);

    for (int ch = 0; ch < nch; ++ch) {
        const int s = ch & 1;
        if (ch + 1 < nch) {
            prefetch(ch + 1, s ^ 1);
            CP_WAIT(1);
        } else {
            CP_WAIT(0);
        }
        __syncthreads();

        const uint32_t base = sb + s * GSTAGE;
        #pragma unroll
        for (int ks = 0; ks < KSTEP; ks += 16) {
            uint32_t afh[2][4], afl[2][4];
            #pragma unroll
            for (int mt = 0; mt < 2; ++mt) {
                int ar = wm * 32 + mt * 16 + (lane & 15);
                int ac = ks + ((lane >> 4) << 3);
                uint32_t a0 = base + (ar * SPAD + ac) * 2;
                ldsm4(afh[mt][0], afh[mt][1], afh[mt][2], afh[mt][3], a0);
                ldsm4(afl[mt][0], afl[mt][1], afl[mt][2], afl[mt][3], a0 + GST);
            }
            #pragma unroll
            for (int p = 0; p < 4; ++p) {
                int br = wn * 64 + p * 16 + (lane & 7) + ((lane >> 4) << 3);
                int bc = ks + (((lane >> 3) & 1) << 3);
                uint32_t b0a = base + 2 * GST + (br * SPAD + bc) * 2;
                uint32_t bh0, bh1, bh2, bh3, bl0, bl1, bl2, bl3;
                ldsm4(bh0, bh1, bh2, bh3, b0a);
                ldsm4(bl0, bl1, bl2, bl3, b0a + GST);
                #pragma unroll
                for (int mt = 0; mt < 2; ++mt) {
                    mma16816(c[mt][2 * p], afh[mt][0], afh[mt][1], afh[mt][2], afh[mt][3], bh0, bh1);
                    mma16816(c[mt][2 * p], afh[mt][0], afh[mt][1], afh[mt][2], afh[mt][3], bl0, bl1);
                    mma16816(c[mt][2 * p], afl[mt][0], afl[mt][1], afl[mt][2], afl[mt][3], bh0, bh1);
                    mma16816(c[mt][2 * p + 1], afh[mt][0], afh[mt][1], afh[mt][2], afh[mt][3], bh2, bh3);
                    mma16816(c[mt][2 * p + 1], afh[mt][0], afh[mt][1], afh[mt][2], afh[mt][3], bl2, bl3);
                    mma16816(c[mt][2 * p + 1], afl[mt][0], afl[mt][1], afl[mt][2], afl[mt][3], bh2, bh3);
                }
            }
        }
        __syncthreads();
    }

    // epilogue (from registers)
    const int r  = lane >> 2;
    const int cq = (lane & 3) * 2;
    #pragma unroll
    for (int mt = 0; mt < 2; ++mt) {
        #pragma unroll
        for (int nt = 0; nt < 8; ++nt) {
            int row = m0 + wm * 32 + mt * 16 + r;
            int col = n0 + wn * 64 + nt * 8 + cq;
            float* cc = c[mt][nt];
            if (mode == 0) {
                float b0 = bias[col], b1 = bias[col + 1];
                *(float2*)&Cf[(size_t)row * N + col] = make_float2(cc[0] + b0, cc[1] + b1);
                *(float2*)&Cf[(size_t)(row + 8) * N + col] = make_float2(cc[2] + b0, cc[3] + b1);
            } else if (mode == 1) {
                uint32_t h, l;
                split_pack(cc[0], cc[1], h, l);
                *(uint32_t*)&Chi[(size_t)row * N + col] = h;
                *(uint32_t*)&Clo[(size_t)row * N + col] = l;
                split_pack(cc[2], cc[3], h, l);
                *(uint32_t*)&Chi[(size_t)(row + 8) * N + col] = h;
                *(uint32_t*)&Clo[(size_t)(row + 8) * N + col] = l;
            } else {
                if (col < DHEAD) {
                    uint32_t h, l;
                    split_pack(cc[0], cc[1], h, l);
                    *(uint32_t*)&Khi[(size_t)row * DHEAD + col] = h;
                    *(uint32_t*)&Klo[(size_t)row * DHEAD + col] = l;
                    split_pack(cc[2], cc[3], h, l);
                    *(uint32_t*)&Khi[(size_t)(row + 8) * DHEAD + col] = h;
                    *(uint32_t*)&Klo[(size_t)(row + 8) * DHEAD + col] = l;
                } else {
                    int d = col - DHEAD;
                    int b = row >> 11, tok = row & 2047;
                    #pragma unroll
                    for (int e = 0; e < 2; ++e) {
                        __nv_bfloat16 h, l;
                        size_t base2 = ((size_t)(b * DHEAD + d + e)) * N_TOK;
                        split1(cc[e], h, l);
                        Vth[base2 + tok] = h; Vtl[base2 + tok] = l;
                        split1(cc[2 + e], h, l);
                        Vth[base2 + tok + 8] = h; Vtl[base2 + tok + 8] = l;
                    }
                }
            }
        }
    }
}

// ---------------- flash attention, cp.async-pipelined K/V ------------------
// CTA: 128 q-rows x one (b,h); 8 warps x 16 q-rows. kv chunks of 64, double-
// buffered via cp.async. S/P stay in fragments; P split in-register.
#define QPAD2   72                        // 144-B rows (LDSM conflict-free)
#define AQ_OFF  0
#define AQL_OFF (128 * QPAD2 * 2)         // 18432
#define AKV_OFF (2 * 128 * QPAD2 * 2)     // 36864
#define AKVST   (64 * QPAD2 * 2)          // 9216 B per array per stage
#define AKVSTAGE (4 * AKVST)              // 36864 B per stage
#define ASMEM   (AKV_OFF + 2 * AKVSTAGE)  // 110592 B

__global__ __launch_bounds__(256, 2) void attn_mma(
    const __nv_bfloat16* __restrict__ qh, const __nv_bfloat16* __restrict__ ql,
    const __nv_bfloat16* __restrict__ kh, const __nv_bfloat16* __restrict__ kl,
    const __nv_bfloat16* __restrict__ vth, const __nv_bfloat16* __restrict__ vtl,
    __nv_bfloat16* __restrict__ oh, __nv_bfloat16* __restrict__ ol)
{
    extern __shared__ char smem[];
    const uint32_t sb = smem_u32(smem);

    const int tid  = threadIdx.x;
    const int lane = tid & 31;
    const int wid  = tid >> 5;
    const int q0   = blockIdx.x << 7;
    const int h    = blockIdx.y;
    const int b    = blockIdx.z;
    const int wrow = wid * 16;

    // Q tile (128 x 64) hi+lo, plain loads
    {
        __nv_bfloat16* Qh = (__nv_bfloat16*)(smem + AQ_OFF);
        __nv_bfloat16* Ql = (__nv_bfloat16*)(smem + AQL_OFF);
        #pragma unroll
        for (int it = 0; it < 4; ++it) {
            int e = tid + it * 256;
            int row = e >> 3, ch = e & 7;
            size_t g = (size_t)(b * N_TOK + q0 + row) * INNER + h * DHEAD + ch * 8;
            int s = row * QPAD2 + ch * 8;
            *(uint4*)&Qh[s] = *(const uint4*)&qh[g];
            *(uint4*)&Ql[s] = *(const uint4*)&ql[g];
        }
    }

    auto prefetch_kv = [&](int chunk, int s) {
        const uint32_t base = sb + AKV_OFF + s * AKVSTAGE;
        const int kv0 = chunk * 64;
        #pragma unroll
        for (int it = 0; it < 2; ++it) {
            int e = tid + it * 256;          // 0..511
            int row = e >> 3, ch = e & 7;
            size_t gk = (size_t)(b * N_TOK + kv0 + row) * DHEAD + ch * 8;
            size_t gv = (size_t)(b * DHEAD + row) * N_TOK + kv0 + ch * 8;
            uint32_t so = row * (QPAD2 * 2) + ch * 16;
            CP16(base + so,             &kh[gk]);
            CP16(base + AKVST + so,     &kl[gk]);
            CP16(base + 2 * AKVST + so, &vth[gv]);
            CP16(base + 3 * AKVST + so, &vtl[gv]);
        }
        CP_COMMIT();
    };

    float oc[8][4];
    #pragma unroll
    for (int j = 0; j < 8; ++j)
        #pragma unroll
        for (int q = 0; q < 4; ++q) oc[j][q] = 0.f;
    float mst[2] = {-CUDART_INF_F, -CUDART_INF_F};
    float lst[2] = {0.f, 0.f};

    const int NCH = N_TOK / 64;     // 32
    prefetch_kv(0, 0);

    for (int chk = 0; chk < NCH; ++chk) {
        const int s = chk & 1;
        if (chk + 1 < NCH) {
            prefetch_kv(chk + 1, s ^ 1);
            CP_WAIT(1);
        } else {
            CP_WAIT(0);
        }
        __syncthreads();   // KV stage ready; also covers Q store on chk==0,
                           // and prior-iteration compute done before its reuse

        const uint32_t qhB = sb + AQ_OFF;
        const uint32_t qlB = sb + AQL_OFF;
        const uint32_t khB = sb + AKV_OFF + s * AKVSTAGE;
        const uint32_t klB = khB + AKVST;
        const uint32_t vhB = khB + 2 * AKVST;
        const uint32_t vlB = khB + 3 * AKVST;

        // ---- S = Q @ K^T ----
        float sc[8][4];
        #pragma unroll
        for (int j = 0; j < 8; ++j)
            #pragma unroll
            for (int q = 0; q < 4; ++q) sc[j][q] = 0.f;

        #pragma unroll
        for (int ks = 0; ks < 4; ++ks) {
            uint32_t ah0[4], al0[4];
            int ar = wrow + (lane & 15);
            int ac = ks * 16 + ((lane >> 4) << 3);
            uint32_t qa = (ar * QPAD2 + ac) * 2;
            ldsm4(ah0[0], ah0[1], ah0[2], ah0[3], qhB + qa);
            ldsm4(al0[0], al0[1], al0[2], al0[3], qlB + qa);
            #pragma unroll
            for (int p = 0; p < 4; ++p) {
                int br = p * 16 + (lane & 7) + ((lane >> 4) << 3);
                int bc = ks * 16 + (((lane >> 3) & 1) << 3);
                uint32_t ka = (br * QPAD2 + bc) * 2;
                uint32_t bh0, bh1, bh2, bh3, bl0, bl1, bl2, bl3;
                ldsm4(bh0, bh1, bh2, bh3, khB + ka);
                ldsm4(bl0, bl1, bl2, bl3, klB + ka);
                mma16816(sc[2 * p],     ah0[0], ah0[1], ah0[2], ah0[3], bh0, bh1);
                mma16816(sc[2 * p],     ah0[0], ah0[1], ah0[2], ah0[3], bl0, bl1);
                mma16816(sc[2 * p],     al0[0], al0[1], al0[2], al0[3], bh0, bh1);
                mma16816(sc[2 * p + 1], ah0[0], ah0[1], ah0[2], ah0[3], bh2, bh3);
                mma16816(sc[2 * p + 1], ah0[0], ah0[1], ah0[2], ah0[3], bl2, bl3);
                mma16816(sc[2 * p + 1], al0[0], al0[1], al0[2], al0[3], bh2, bh3);
            }
        }

        // ---- online softmax on fragments ----
        #pragma unroll
        for (int hf = 0; hf < 2; ++hf) {
            float mx = -CUDART_INF_F;
            #pragma unroll
            for (int nt = 0; nt < 8; ++nt) {
                sc[nt][2 * hf]     *= SCALE_F;
                sc[nt][2 * hf + 1] *= SCALE_F;
                mx = fmaxf(mx, fmaxf(sc[nt][2 * hf], sc[nt][2 * hf + 1]));
            }
            mx = fmaxf(mx, __shfl_xor_sync(0xffffffffu, mx, 1));
            mx = fmaxf(mx, __shfl_xor_sync(0xffffffffu, mx, 2));
            float mn = fmaxf(mst[hf], mx);
            float alpha = __expf(mst[hf] - mn);
            float sum = 0.f;
            #pragma unroll
            for (int nt = 0; nt < 8; ++nt) {
                float p0 = __expf(sc[nt][2 * hf] - mn);
                float p1 = __expf(sc[nt][2 * hf + 1] - mn);
                sc[nt][2 * hf] = p0; sc[nt][2 * hf + 1] = p1;
                sum += p0 + p1;
            }
            sum += __shfl_xor_sync(0xffffffffu, sum, 1);
            sum += __shfl_xor_sync(0xffffffffu, sum, 2);
            lst[hf] = lst[hf] * alpha + sum;
            mst[hf] = mn;
            #pragma unroll
            for (int nt = 0; nt < 8; ++nt) {
                oc[nt][2 * hf]     *= alpha;
                oc[nt][2 * hf + 1] *= alpha;
            }
        }

        // ---- O += P @ V ----
        #pragma unroll
        for (int kt = 0; kt < 4; ++kt) {
            uint32_t pah[4], pal[4];
            split_pack(sc[2 * kt][0],     sc[2 * kt][1],     pah[0], pal[0]);
            split_pack(sc[2 * kt][2],     sc[2 * kt][3],     pah[1], pal[1]);
            split_pack(sc[2 * kt + 1][0], sc[2 * kt + 1][1], pah[2], pal[2]);
            split_pack(sc[2 * kt + 1][2], sc[2 * kt + 1][3], pah[3], pal[3]);
            #pragma unroll
            for (int p = 0; p < 4; ++p) {
                int br = p * 16 + (lane & 7) + ((lane >> 4) << 3);
                int bc = kt * 16 + (((lane >> 3) & 1) << 3);
                uint32_t va = (br * QPAD2 + bc) * 2;
                uint32_t vh0, vh1, vh2, vh3, vl0, vl1, vl2, vl3;
                ldsm4(vh0, vh1, vh2, vh3, vhB + va);
                ldsm4(vl0, vl1, vl2, vl3, vlB + va);
                mma16816(oc[2 * p],     pah[0], pah[1], pah[2], pah[3], vh0, vh1);
                mma16816(oc[2 * p],     pah[0], pah[1], pah[2], pah[3], vl0, vl1);
                mma16816(oc[2 * p],     pal[0], pal[1], pal[2], pal[3], vh0, vh1);
                mma16816(oc[2 * p + 1], pah[0], pah[1], pah[2], pah[3], vh2, vh3);
                mma16816(oc[2 * p + 1], pah[0], pah[1], pah[2], pah[3], vl2, vl3);
                mma16816(oc[2 * p + 1], pal[0], pal[1], pal[2], pal[3], vh2, vh3);
            }
        }
        __syncthreads();   // compute done before stage s is refilled
    }

    // ---- epilogue: normalize, split, write ----
    float inv0 = 1.f / lst[0], inv1 = 1.f / lst[1];
    const int r  = lane >> 2;
    const int cq = (lane & 3) * 2;
    #pragma unroll
    for (int nt = 0; nt < 8; ++nt) {
        int row = b * N_TOK + q0 + wrow + r;
        int col = h * DHEAD + nt * 8 + cq;
        uint32_t hw, lw;
        split_pack(oc[nt][0] * inv0, oc[nt][1] * inv0, hw, lw);
        *(uint32_t*)&oh[(size_t)row * INNER + col] = hw;
        *(uint32_t*)&ol[(size_t)row * INNER + col] = lw;
        split_pack(oc[nt][2] * inv1, oc[nt][3] * inv1, hw, lw);
        *(uint32_t*)&oh[(size_t)(row + 8) * INNER + col] = hw;
        *(uint32_t*)&ol[(size_t)(row + 8) * INNER + col] = lw;
    }
}

// ---------------------------------------------------------------------------
extern "C" void kernel_launch(void* const* d_in, const int* in_sizes, int n_in,
                              void* d_out, int out_size)
{
    (void)in_sizes; (void)n_in; (void)out_size;
    const float* x     = (const float*)d_in[0];
    const float* w_q   = (const float*)d_in[1];
    const float* w_kv  = (const float*)d_in[2];
    const float* w_out = (const float*)d_in[3];
    const float* b_out = (const float*)d_in[4];
    float* out = (float*)d_out;

    __nv_bfloat16 *xh, *xl, *wqh, *wql, *wkh, *wkl, *woh, *wol;
    __nv_bfloat16 *qhp, *qlp, *khp, *klp, *vth, *vtl, *ahp, *alp;
    cudaGetSymbolAddress((void**)&xh,  g_xh);  cudaGetSymbolAddress((void**)&xl,  g_xl);
    cudaGetSymbolAddress((void**)&wqh, g_wqh); cudaGetSymbolAddress((void**)&wql, g_wql);
    cudaGetSymbolAddress((void**)&wkh, g_wkh); cudaGetSymbolAddress((void**)&wkl, g_wkl);
    cudaGetSymbolAddress((void**)&woh, g_woh); cudaGetSymbolAddress((void**)&wol, g_wol);
    cudaGetSymbolAddress((void**)&qhp, g_qh);  cudaGetSymbolAddress((void**)&qlp, g_ql);
    cudaGetSymbolAddress((void**)&khp, g_kh);  cudaGetSymbolAddress((void**)&klp, g_kl);
    cudaGetSymbolAddress((void**)&vth, g_vth); cudaGetSymbolAddress((void**)&vtl, g_vtl);
    cudaGetSymbolAddress((void**)&ahp, g_ah);  cudaGetSymbolAddress((void**)&alp, g_al);

    // 1. split x; transpose+split weights
    split_f32<<<(MROWS * DIM / 4 + 255) / 256, 256>>>(
        (const float4*)x, (uint2*)xh, (uint2*)xl, MROWS * DIM / 4);
    transpose_split<<<dim3(INNER / 32, DIM / 32), dim3(32, 8)>>>(w_q,  wqh, wql, DIM, INNER);
    transpose_split<<<dim3((2 * DHEAD) / 32, DIM / 32), dim3(32, 8)>>>(w_kv, wkh, wkl, DIM, 2 * DHEAD);
    transpose_split<<<dim3(DIM / 32, INNER / 32), dim3(32, 8)>>>(w_out, woh, wol, INNER, DIM);

    cudaFuncSetAttribute(gemm_cp, cudaFuncAttributeMaxDynamicSharedMemorySize, GSMEM);

    // 2. Q projection (mode 1)
    gemm_cp<<<dim3(INNER / 128, MROWS / 128), 256, GSMEM>>>(
        xh, xl, wqh, wql, nullptr, nullptr, qhp, qlp,
        nullptr, nullptr, nullptr, nullptr, MROWS, INNER, DIM, 1);
    // 3. KV projection (mode 2)
    gemm_cp<<<dim3(1, MROWS / 128), 256, GSMEM>>>(
        xh, xl, wkh, wkl, nullptr, nullptr, nullptr, nullptr,
        khp, klp, vth, vtl, MROWS, 2 * DHEAD, DIM, 2);

    // 4. attention (pipelined)
    cudaFuncSetAttribute(attn_mma, cudaFuncAttributeMaxDynamicSharedMemorySize, ASMEM);
    attn_mma<<<dim3(N_TOK / 128, HEADS, BATCH), 256, ASMEM>>>(
        qhp, qlp, khp, klp, vth, vtl, ahp, alp);

    // 5. output projection + bias (mode 0)
    gemm_cp<<<dim3(DIM / 128, MROWS / 128), 256, GSMEM>>>(
        ahp, alp, woh, wol, b_out, out, nullptr, nullptr,
        nullptr, nullptr, nullptr, nullptr, MROWS, DIM, INNER, 0);
}